// round 12
// baseline (speedup 1.0000x reference)
#include <cuda_runtime.h>
#include <cstdint>

// UpsampleNearest4D: x (2,8,8,16,64,64) f32, x2 on axes 2..5.
// Output (2,8,16,32,128,128).
//
// R8: bulk-async store path. Each block handles one (nc,t,z,y16) chunk:
//   - 512 threads load 16 input rows (1 float2 each, 4KB total)
//   - expand x (dup within float4) and y (two SMEM rows) into a 16KB
//     contiguous SMEM slab (32 output rows x 512B)
//   - elected thread issues 4 x 16KB cp.async.bulk (z- and t-duplicates),
//     each to a fully contiguous GMEM range.
// DRAM write stream becomes 16KB contiguous bursts from the async copy
// hardware instead of scattered per-lane STG.128s.

__global__ __launch_bounds__(512) void upsample4d_bulk_kernel(
    const float2* __restrict__ in, char* __restrict__ out)
{
    __shared__ __align__(128) float4 buf[32 * 32];   // 16 KB: 32 rows x 512B

    unsigned bid = blockIdx.x;          // [0, 8192)
    unsigned y16 = bid & 3u;            // which 16-row y chunk
    unsigned r   = bid >> 2;
    unsigned z   = r & 15u;  r >>= 4;
    unsigned t   = r & 7u;
    unsigned nc  = r >> 3;              // [0,16)

    unsigned tid = threadIdx.x;
    unsigned x2  = tid & 31u;           // input float2 column
    unsigned yl  = tid >> 5;            // local input row [0,16)

    unsigned iy   = y16 * 16u + yl;
    unsigned iidx = ((((nc * 8u + t) * 16u + z) * 64u + iy) * 32u) + x2;

    float2 v = __ldg(&in[iidx]);
    float4 o = make_float4(v.x, v.x, v.y, v.y);

    // y-duplicate into two adjacent SMEM rows (32 f4 per row)
    buf[(yl * 2u)      * 32u + x2] = o;
    buf[(yl * 2u + 1u) * 32u + x2] = o;

    __syncthreads();
    // order generic SMEM stores before async-proxy bulk reads
    asm volatile("fence.proxy.async.shared::cta;" ::: "memory");

    if (tid == 0) {
        uint32_t s;
        asm("{ .reg .u64 tmp; cvta.to.shared.u64 tmp, %1; cvt.u32.u64 %0, tmp; }"
            : "=r"(s) : "l"(buf));

        const unsigned CHUNK = 16384u;  // 32 rows x 512B
        // destination f4 base for (dt, dz): contiguous 16KB each
        #pragma unroll
        for (unsigned dt = 0; dt < 2u; dt++) {
            #pragma unroll
            for (unsigned dz = 0; dz < 2u; dz++) {
                unsigned ot = 2u * t + dt;
                unsigned oz = 2u * z + dz;
                size_t base_f4 = (size_t)(((nc * 16u + ot) * 32u + oz) * 128u
                                          + y16 * 32u) * 32u;
                char* dst = out + base_f4 * 16u;
                asm volatile(
                    "cp.async.bulk.global.shared::cta.bulk_group [%0], [%1], %2;"
                    :: "l"(dst), "r"(s), "r"(CHUNK)
                    : "memory");
            }
        }
        asm volatile("cp.async.bulk.commit_group;" ::: "memory");
        asm volatile("cp.async.bulk.wait_group 0;" ::: "memory");
    }
}

extern "C" void kernel_launch(void* const* d_in, const int* in_sizes, int n_in,
                              void* d_out, int out_size)
{
    const float2* in = (const float2*)d_in[0];
    char* out = (char*)d_out;

    // 16(nc) * 8(t) * 16(z) * 4(y16) = 8192 blocks
    upsample4d_bulk_kernel<<<8192u, 512u>>>(in, out);
}

// round 13
// speedup vs baseline: 1.0265x; 1.0265x over previous
#include <cuda_runtime.h>
#include <cstdint>

// UpsampleNearest4D: x (2,8,8,16,64,64) f32, x2 on axes 2..5.
// Output (2,8,16,32,128,128).
//
// FINAL (R5 config). Input-driven: one thread per input float2; eight
// independent STG.128 {a,a,b,b} stores cover the 2x2x2x2 (t,z,y,x)
// duplication. Each warp-store is 512B contiguous; every output 128B
// line is fully written by a single instruction (no read-for-ownership).
// Stores are .cs (evict-first): the 512MB write stream is write-once.
//
// Plateau evidence (rounds 1-12): STG.128 x8 (71.4% DRAM), STG.256 x8
// (69.0%), output-driven linear (59.7%), split two-pass (63.5%/half),
// 16-deep stores (70.4%), cp.async.bulk 16KB bursts (71.7%) -- the
// ~5.9 TB/s mixed-stream ceiling is path-independent. Traffic is at the
// algorithmic minimum (570MB), so ~87us is the floor on this part.

__global__ __launch_bounds__(512) void upsample4d_kernel(
    const float2* __restrict__ in, float4* __restrict__ out)
{
    unsigned idx = blockIdx.x * 512u + threadIdx.x;   // [0, 4194304)

    unsigned x2 = idx & 31u;            // float2 column within input row
    unsigned r  = idx >> 5;
    unsigned y  = r & 63u;  r >>= 6;
    unsigned z  = r & 15u;  r >>= 4;
    unsigned t  = r & 7u;   r >>= 3;
    unsigned nc = r;                    // [0,16)

    float2 v = __ldg(&in[idx]);
    float4 o = make_float4(v.x, v.x, v.y, v.y);

    // Output strides in float4 units: row = 128/4 = 32
    const unsigned SY = 32u;                 // one output row (512B)
    const unsigned SZ = 128u * 32u;          // OY rows
    const unsigned ST = 32u * 128u * 32u;    // OZ * OY rows

    unsigned base = ((((nc * 16u + 2u * t) * 32u + 2u * z) * 128u + 2u * y) * 32u) + x2;

    float4* p0 = out + base;
    float4* p1 = out + base + ST;

    #define STCS(ptr) asm volatile( \
        "st.global.cs.v4.f32 [%0], {%1,%2,%3,%4};" \
        :: "l"(ptr), "f"(o.x), "f"(o.y), "f"(o.z), "f"(o.w) : "memory")

    STCS(p0);
    STCS(p0 + SY);
    STCS(p0 + SZ);
    STCS(p0 + SZ + SY);
    STCS(p1);
    STCS(p1 + SY);
    STCS(p1 + SZ);
    STCS(p1 + SZ + SY);

    #undef STCS
}

extern "C" void kernel_launch(void* const* d_in, const int* in_sizes, int n_in,
                              void* d_out, int out_size)
{
    const float2* in = (const float2*)d_in[0];
    float4* out = (float4*)d_out;

    // 8,388,608 input floats -> 4,194,304 float2 threads
    const unsigned n_threads = 8u * 1024u * 1024u / 2u;
    upsample4d_kernel<<<n_threads / 512u, 512u>>>(in, out);
}